// round 4
// baseline (speedup 1.0000x reference)
#include <cuda_runtime.h>
#include <cstdint>

// ---------------------------------------------------------------------------
// y[bi,co,ti,p] = sum_{ds,dt,ci} W[co,ci,ds,dt]*x[bi',ci,t2,p] + x
// tf32 mma.sync m16n8k8 implicit GEMM (tcgen05 not reachable: harness PTX
// target is sm_100 without 'a').
// A = g_Wt[tap][co][ci'] (K-major), B = g_Xt[z][p][ci'] (K-major, p pad 224),
// where ci' applies a within-8 permutation so that the HMMA fragment pair
// (k, k+4) is physically adjacent -> all fragment loads are LDS.64.
// CTA tile: 128(co) x 112(p), BK=32, 3-stage cp.async pipeline.
// ---------------------------------------------------------------------------

#define CCH 1024
#define TT 4
#define HW 196
#define NPAD 224
#define SSEG 4
#define BM 128
#define BN 112
#define BKI 32
#define PADW 36                       // smem row width in floats

#define ASZ (BM * PADW)
#define BSZ (BN * PADW)
#define STAGE_FLOATS (ASZ + BSZ)
#define SMEM_REQ (3 * STAGE_FLOATS * 4)   // 103680 B, 2 CTAs/SM fits 228KB

__device__ float g_Wt[9u * CCH * CCH];      // [tap][co][ci'], tf32-rounded
__device__ float g_Xt[32u * NPAD * CCH];    // [z][p][ci'],    tf32-rounded

// within-8 K permutation: logical j -> phys (j&3)*2 + (j>>2)
__device__ __forceinline__ int kperm(int ci) {
    int j = ci & 7;
    return (ci & ~7) | (((j & 3) << 1) | (j >> 2));
}

// ---------------------------- helpers --------------------------------------
__device__ __forceinline__ uint32_t f2tf32(float a) {
    uint32_t r; asm("cvt.rna.tf32.f32 %0, %1;" : "=r"(r) : "f"(a)); return r;
}
__device__ __forceinline__ void cp16(uint32_t dst, const void* src) {
    asm volatile("cp.async.cg.shared.global [%0], [%1], 16;" :: "r"(dst), "l"(src));
}
#define CP_COMMIT() asm volatile("cp.async.commit_group;" ::: "memory")
#define CP_WAIT2()  asm volatile("cp.async.wait_group 2;" ::: "memory")

__device__ __forceinline__ void mma_tf32(float* c, const uint32_t* a, const uint32_t* b) {
    asm volatile(
        "mma.sync.aligned.m16n8k8.row.col.f32.tf32.tf32.f32 "
        "{%0,%1,%2,%3}, {%4,%5,%6,%7}, {%8,%9}, {%0,%1,%2,%3};"
        : "+f"(c[0]), "+f"(c[1]), "+f"(c[2]), "+f"(c[3])
        : "r"(a[0]), "r"(a[1]), "r"(a[2]), "r"(a[3]), "r"(b[0]), "r"(b[1]));
}

// ---------------------------- prep kernels ---------------------------------
// g_Wt[tap][co][kperm(ci)] = tf32(W[co][ci][tap])
__global__ __launch_bounds__(256) void prep_w(const float* __restrict__ W) {
    __shared__ float s[9216];
    int co = blockIdx.x;
    const float4* row4 = (const float4*)(W + (size_t)co * 9216);
    float4* s4 = (float4*)s;
    for (int i = threadIdx.x; i < 2304; i += 256) s4[i] = row4[i];
    __syncthreads();
    uint32_t* dst = (uint32_t*)g_Wt;
    for (int tap = 0; tap < 9; tap++) {
        uint32_t* d = dst + ((size_t)tap * CCH + co) * CCH;
        for (int ci = threadIdx.x; ci < CCH; ci += 256)
            d[kperm(ci)] = f2tf32(s[ci * 9 + tap]);
    }
}

// g_Xt[z][p][kperm(ci)] = tf32(x[bi][ci][t][p]); p in [196,224) -> 0
__global__ void prep_x(const float* __restrict__ x) {
    __shared__ float tile[32][33];
    int z = blockIdx.z;                    // bi*4 + t
    int p0 = blockIdx.x * 32;              // 7 tiles -> 224
    int ci0 = blockIdx.y * 32;
    int tx = threadIdx.x, ty = threadIdx.y;   // 32 x 8
    #pragma unroll
    for (int j = 0; j < 4; j++) {
        int ci = ci0 + ty + j * 8;
        int p = p0 + tx;
        float v = 0.f;
        if (p < HW) v = x[(((size_t)((z >> 2) * CCH + ci)) * TT + (z & 3)) * HW + p];
        tile[ty + j * 8][tx] = v;
    }
    __syncthreads();
    uint32_t* dst = (uint32_t*)g_Xt;
    #pragma unroll
    for (int j = 0; j < 4; j++) {
        int p = p0 + ty + j * 8;
        int ci = ci0 + tx;
        dst[((size_t)z * NPAD + p) * CCH + kperm(ci)] = f2tf32(tile[tx][ty + j * 8]);
    }
}

// ---------------------------- main kernel -----------------------------------
__global__ __launch_bounds__(256, 2) void conv_mma(
    const float* __restrict__ x, float* __restrict__ out)
{
    extern __shared__ float smem[];
    const int tid = threadIdx.x;
    const int wid = tid >> 5, lid = tid & 31;
    const int gid = lid >> 2, tig = lid & 3;
    const int warp_m = wid & 3;           // 4 warps in M: 32 rows each
    const int warp_n = wid >> 2;          // 2 warps in N: 56 cols each

    const int ct = blockIdx.x >> 1;       // co tile 0..7
    const int py = blockIdx.x & 1;        // p tile 0..1
    const int z  = blockIdx.y;            // bi*4 + ti
    const int bi = z >> 2, ti = z & 3;
    const int s_seg = bi & 3, bp = bi >> 2;
    const int co0 = ct * BM;
    const int p0  = py * BN;

    // valid taps
    int taps[9], zsrc[9], nv = 0;
    #pragma unroll
    for (int ds = 0; ds < 3; ds++) {
        int s2 = s_seg + ds - 1;
        if (s2 < 0 || s2 >= SSEG) continue;
        #pragma unroll
        for (int dt = 0; dt < 3; dt++) {
            int t2 = ti + dt - 1;
            if (t2 < 0 || t2 >= TT) continue;
            taps[nv] = ds * 3 + dt;
            zsrc[nv] = (bp * SSEG + s2) * TT + t2;
            nv++;
        }
    }
    const int total = nv * (CCH / BKI);

    uint32_t smem_u = (uint32_t)__cvta_generic_to_shared(smem);

    float acc[2][7][4];
    #pragma unroll
    for (int mt = 0; mt < 2; mt++)
        #pragma unroll
        for (int nt = 0; nt < 7; nt++)
            #pragma unroll
            for (int r = 0; r < 4; r++) acc[mt][nt][r] = 0.f;

    auto load_stage = [&](int it, int st) {
        int idx = it >> 5, k0 = (it & 31) * BKI;
        const float* Wt = g_Wt + (size_t)taps[idx] * CCH * CCH + (size_t)co0 * CCH + k0;
        const float* Xz = g_Xt + (size_t)zsrc[idx] * NPAD * CCH + (size_t)p0 * CCH + k0;
        uint32_t aB = smem_u + st * (STAGE_FLOATS * 4);
        uint32_t bB = aB + ASZ * 4;
        #pragma unroll
        for (int i = 0; i < 4; i++) {
            int c = tid + i * 256;
            int row = c >> 3, cc = c & 7;
            cp16(aB + row * (PADW * 4) + cc * 16, Wt + (size_t)row * CCH + cc * 4);
        }
        #pragma unroll
        for (int i = 0; i < 4; i++) {
            int c = tid + i * 256;
            if (c < BN * 8) {
                int row = c >> 3, cc = c & 7;
                cp16(bB + row * (PADW * 4) + cc * 16, Xz + (size_t)row * CCH + cc * 4);
            }
        }
    };

    load_stage(0, 0); CP_COMMIT();
    load_stage(1, 1); CP_COMMIT();

    int st = 0;
    for (int it = 0; it < total; it++) {
        if (it + 2 < total) load_stage(it + 2, (st + 2 >= 3) ? st - 1 : st + 2);
        CP_COMMIT();
        CP_WAIT2();
        __syncthreads();

        const float* As = smem + st * STAGE_FLOATS;
        const float* Bs = As + ASZ;
        #pragma unroll
        for (int ks = 0; ks < 4; ks++) {
            const int pb = ks * 8 + tig * 2;      // phys offset of (k, k+4) pair
            uint32_t a[2][4], b[7][2];
            #pragma unroll
            for (int mt = 0; mt < 2; mt++) {
                const uint2* r0 = (const uint2*)(As + (warp_m * 32 + mt * 16 + gid) * PADW + pb);
                const uint2* r1 = (const uint2*)(As + (warp_m * 32 + mt * 16 + gid + 8) * PADW + pb);
                uint2 v0 = *r0, v1 = *r1;
                a[mt][0] = v0.x; a[mt][1] = v1.x; a[mt][2] = v0.y; a[mt][3] = v1.y;
            }
            #pragma unroll
            for (int nt = 0; nt < 7; nt++) {
                uint2 v = *(const uint2*)(Bs + (warp_n * 56 + nt * 8 + gid) * PADW + pb);
                b[nt][0] = v.x; b[nt][1] = v.y;
            }
            #pragma unroll
            for (int mt = 0; mt < 2; mt++)
                #pragma unroll
                for (int nt = 0; nt < 7; nt++)
                    mma_tf32(acc[mt][nt], a[mt], b[nt]);
        }
        __syncthreads();
        st = (st + 1 >= 3) ? 0 : st + 1;
    }

    // epilogue: residual add + store
    #pragma unroll
    for (int mt = 0; mt < 2; mt++) {
        #pragma unroll
        for (int nt = 0; nt < 7; nt++) {
            int co = co0 + warp_m * 32 + mt * 16 + gid;
            int p  = p0 + warp_n * 56 + nt * 8 + tig * 2;
            if (p < HW) {
                size_t i0 = ((size_t)(bi * CCH + co) * TT + ti) * HW + p;
                float2 r0 = *(const float2*)&x[i0];
                float2 o0 = { acc[mt][nt][0] + r0.x, acc[mt][nt][1] + r0.y };
                *(float2*)&out[i0] = o0;
                size_t i1 = ((size_t)(bi * CCH + co + 8) * TT + ti) * HW + p;
                float2 r1 = *(const float2*)&x[i1];
                float2 o1 = { acc[mt][nt][2] + r1.x, acc[mt][nt][3] + r1.y };
                *(float2*)&out[i1] = o1;
            }
        }
    }
}

// ---------------------------- host launch -----------------------------------
extern "C" void kernel_launch(void* const* d_in, const int* in_sizes, int n_in,
                              void* d_out, int out_size) {
    const float* x = (const float*)d_in[0];   // (8,1024,4,14,14)
    const float* W = (const float*)d_in[1];   // (1024,1024,3,3)
    float* out = (float*)d_out;

    prep_w<<<CCH, 256>>>(W);
    prep_x<<<dim3(7, 32, 32), dim3(32, 8)>>>(x);

    cudaFuncSetAttribute(conv_mma, cudaFuncAttributeMaxDynamicSharedMemorySize, SMEM_REQ);
    conv_mma<<<dim3(16, 32), 256, SMEM_REQ>>>(x, out);
}

// round 5
// speedup vs baseline: 1.4101x; 1.4101x over previous
#include <cuda_runtime.h>
#include <cstdint>

// ---------------------------------------------------------------------------
// y[bi,co,ti,p] = sum_{ds,dt,ci} W[co,ci,ds,dt]*x[bi',ci,t2,p] + x
// tf32 mma.sync m16n8k8 implicit GEMM (tcgen05 unreachable: harness targets
// sm_100 without 'a'). R3 structure (2-stage cp.async, conflict-free 32-bit
// LDS @ PADW=36) + N-pad 200 (asymmetric 112/88 tiles) + cost-sorted blocks.
// ---------------------------------------------------------------------------

#define CCH 1024
#define TT 4
#define HW 196
#define NPAD 200
#define SSEG 4
#define BM 128
#define BN 112
#define BKI 32
#define PADW 36

#define ASZ (BM * PADW)
#define BSZ (BN * PADW)
#define SMEM_REQ (2 * (ASZ + BSZ) * 4)   // 69120 B

__device__ float g_Wt[9u * CCH * CCH];      // [tap][co][ci], tf32-rounded
__device__ float g_Xt[32u * NPAD * CCH];    // [z][p][ci],    tf32-rounded

// work order: heavy (nv=9) z's first, then nv=6, then nv=4
__constant__ int c_zorder[32] = {
    5, 6, 9, 10, 21, 22, 25, 26,          // nv=9
    4, 7, 8, 11, 20, 23, 24, 27,          // nv=6 (s in {1,2})
    1, 2, 13, 14, 17, 18, 29, 30,         // nv=6 (t in {1,2})
    0, 3, 12, 15, 16, 19, 28, 31          // nv=4
};

// ---------------------------- helpers --------------------------------------
__device__ __forceinline__ uint32_t f2tf32(float a) {
    uint32_t r; asm("cvt.rna.tf32.f32 %0, %1;" : "=r"(r) : "f"(a)); return r;
}
__device__ __forceinline__ void cp16(uint32_t dst, const void* src) {
    asm volatile("cp.async.cg.shared.global [%0], [%1], 16;" :: "r"(dst), "l"(src));
}
#define CP_COMMIT() asm volatile("cp.async.commit_group;" ::: "memory")
#define CP_WAIT1()  asm volatile("cp.async.wait_group 1;" ::: "memory")

__device__ __forceinline__ void mma_tf32(float* c, const uint32_t* a, const uint32_t* b) {
    asm volatile(
        "mma.sync.aligned.m16n8k8.row.col.f32.tf32.tf32.f32 "
        "{%0,%1,%2,%3}, {%4,%5,%6,%7}, {%8,%9}, {%0,%1,%2,%3};"
        : "+f"(c[0]), "+f"(c[1]), "+f"(c[2]), "+f"(c[3])
        : "r"(a[0]), "r"(a[1]), "r"(a[2]), "r"(a[3]), "r"(b[0]), "r"(b[1]));
}

// ---------------------------- prep kernels ---------------------------------
__global__ __launch_bounds__(256) void prep_w(const float* __restrict__ W) {
    __shared__ float s[9216];
    int co = blockIdx.x;
    const float4* row4 = (const float4*)(W + (size_t)co * 9216);
    float4* s4 = (float4*)s;
    for (int i = threadIdx.x; i < 2304; i += 256) s4[i] = row4[i];
    __syncthreads();
    uint32_t* dst = (uint32_t*)g_Wt;
    for (int tap = 0; tap < 9; tap++) {
        uint32_t* d = dst + ((size_t)tap * CCH + co) * CCH;
        for (int ci = threadIdx.x; ci < CCH; ci += 256)
            d[ci] = f2tf32(s[ci * 9 + tap]);
    }
}

// g_Xt[z][p][ci] = tf32(x[bi][ci][t][p]); p in [196,200) -> 0
__global__ void prep_x(const float* __restrict__ x) {
    __shared__ float tile[32][33];
    int z = blockIdx.z;                    // bi*4 + t
    int p0 = blockIdx.x * 32;              // 7 tiles, guard at 200
    int ci0 = blockIdx.y * 32;
    int tx = threadIdx.x, ty = threadIdx.y;   // 32 x 8
    #pragma unroll
    for (int j = 0; j < 4; j++) {
        int ci = ci0 + ty + j * 8;
        int p = p0 + tx;
        float v = 0.f;
        if (p < HW) v = x[(((size_t)((z >> 2) * CCH + ci)) * TT + (z & 3)) * HW + p];
        tile[ty + j * 8][tx] = v;
    }
    __syncthreads();
    uint32_t* dst = (uint32_t*)g_Xt;
    #pragma unroll
    for (int j = 0; j < 4; j++) {
        int p = p0 + ty + j * 8;
        int ci = ci0 + tx;
        if (p < NPAD)
            dst[((size_t)z * NPAD + p) * CCH + ci] = f2tf32(tile[tx][ty + j * 8]);
    }
}

// ---------------------------- main kernel -----------------------------------
__global__ __launch_bounds__(256, 2) void conv_mma(
    const float* __restrict__ x, float* __restrict__ out)
{
    extern __shared__ float smem[];
    const int tid = threadIdx.x;
    const int wid = tid >> 5, lid = tid & 31;
    const int gid = lid >> 2, tig = lid & 3;
    const int warp_m = wid & 3;           // 4 warps in M: 32 rows each
    const int warp_n = wid >> 2;          // 2 warps in N

    const int bidl = blockIdx.x;          // 0..511, cost-sorted
    const int z    = c_zorder[bidl >> 4];
    const int tile = bidl & 15;
    const int ct   = tile >> 1;           // co-tile 0..7
    const int py   = tile & 1;            // p-tile 0..1
    const int bi = z >> 2, ti = z & 3;
    const int s_seg = bi & 3, bp = bi >> 2;
    const int co0 = ct * BM;
    const int p0  = py * BN;

    // nt trip count per warp: py=0 -> 7/7 (112 wide); py=1 -> 7/4 (88 wide)
    const int ntc = (py && warp_n) ? 4 : 7;
    const int bnr8 = (py ? 88 : 112) * 8;     // B chunks to load per stage

    // valid taps
    int taps[9], zsrc[9], nv = 0;
    #pragma unroll
    for (int ds = 0; ds < 3; ds++) {
        int s2 = s_seg + ds - 1;
        if (s2 < 0 || s2 >= SSEG) continue;
        #pragma unroll
        for (int dt = 0; dt < 3; dt++) {
            int t2 = ti + dt - 1;
            if (t2 < 0 || t2 >= TT) continue;
            taps[nv] = ds * 3 + dt;
            zsrc[nv] = (bp * SSEG + s2) * TT + t2;
            nv++;
        }
    }
    const int total = nv * (CCH / BKI);

    uint32_t smem_u = (uint32_t)__cvta_generic_to_shared(smem);
    const uint32_t aB[2] = { smem_u, smem_u + ASZ * 4 };
    const uint32_t bB[2] = { smem_u + 2 * ASZ * 4, smem_u + (2 * ASZ + BSZ) * 4 };

    float acc[2][7][4];
    #pragma unroll
    for (int mt = 0; mt < 2; mt++)
        #pragma unroll
        for (int nt = 0; nt < 7; nt++)
            #pragma unroll
            for (int r = 0; r < 4; r++) acc[mt][nt][r] = 0.f;

    auto load_stage = [&](int it, int s) {
        int idx = it >> 5, k0 = (it & 31) * BKI;
        const float* Wt = g_Wt + (size_t)taps[idx] * CCH * CCH + (size_t)co0 * CCH + k0;
        const float* Xz = g_Xt + (size_t)zsrc[idx] * NPAD * CCH + (size_t)p0 * CCH + k0;
        #pragma unroll
        for (int i = 0; i < 4; i++) {
            int c = tid + i * 256;
            int row = c >> 3, cc = c & 7;
            cp16(aB[s] + row * (PADW * 4) + cc * 16, Wt + (size_t)row * CCH + cc * 4);
        }
        #pragma unroll
        for (int i = 0; i < 4; i++) {
            int c = tid + i * 256;
            if (c < bnr8) {
                int row = c >> 3, cc = c & 7;
                cp16(bB[s] + row * (PADW * 4) + cc * 16, Xz + (size_t)row * CCH + cc * 4);
            }
        }
    };

    load_stage(0, 0);
    CP_COMMIT();

    for (int it = 0; it < total; it++) {
        int s = it & 1;
        if (it + 1 < total) load_stage(it + 1, s ^ 1);
        CP_COMMIT();
        CP_WAIT1();
        __syncthreads();

        const float* As = smem + s * ASZ;
        const float* Bs = smem + 2 * ASZ + s * BSZ;
        #pragma unroll
        for (int ks = 0; ks < 4; ks++) {
            int k = ks * 8 + tig;
            uint32_t a[2][4], b[7][2];
            #pragma unroll
            for (int mt = 0; mt < 2; mt++) {
                const uint32_t* ap = (const uint32_t*)(As + (warp_m * 32 + mt * 16 + gid) * PADW + k);
                a[mt][0] = ap[0];
                a[mt][1] = ap[8 * PADW];
                a[mt][2] = ap[4];
                a[mt][3] = ap[8 * PADW + 4];
            }
            #pragma unroll
            for (int nt = 0; nt < 7; nt++) {
                if (nt < ntc) {
                    const uint32_t* bp2 = (const uint32_t*)(Bs + (warp_n * 56 + nt * 8 + gid) * PADW + k);
                    b[nt][0] = bp2[0];
                    b[nt][1] = bp2[4];
                }
            }
            #pragma unroll
            for (int mt = 0; mt < 2; mt++)
                #pragma unroll
                for (int nt = 0; nt < 7; nt++)
                    if (nt < ntc) mma_tf32(acc[mt][nt], a[mt], b[nt]);
        }
        __syncthreads();
    }

    // epilogue: residual add + store
    #pragma unroll
    for (int mt = 0; mt < 2; mt++) {
        #pragma unroll
        for (int nt = 0; nt < 7; nt++) {
            if (nt >= ntc) continue;
            int co = co0 + warp_m * 32 + mt * 16 + gid;
            int p  = p0 + warp_n * 56 + nt * 8 + tig * 2;
            if (p < HW) {
                size_t i0 = ((size_t)(bi * CCH + co) * TT + ti) * HW + p;
                float2 r0 = *(const float2*)&x[i0];
                float2 o0 = { acc[mt][nt][0] + r0.x, acc[mt][nt][1] + r0.y };
                *(float2*)&out[i0] = o0;
                size_t i1 = ((size_t)(bi * CCH + co + 8) * TT + ti) * HW + p;
                float2 r1 = *(const float2*)&x[i1];
                float2 o1 = { acc[mt][nt][2] + r1.x, acc[mt][nt][3] + r1.y };
                *(float2*)&out[i1] = o1;
            }
        }
    }
}

// ---------------------------- host launch -----------------------------------
extern "C" void kernel_launch(void* const* d_in, const int* in_sizes, int n_in,
                              void* d_out, int out_size) {
    const float* x = (const float*)d_in[0];   // (8,1024,4,14,14)
    const float* W = (const float*)d_in[1];   // (1024,1024,3,3)
    float* out = (float*)d_out;

    prep_w<<<CCH, 256>>>(W);
    prep_x<<<dim3(7, 32, 32), dim3(32, 8)>>>(x);

    cudaFuncSetAttribute(conv_mma, cudaFuncAttributeMaxDynamicSharedMemorySize, SMEM_REQ);
    conv_mma<<<512, 256, SMEM_REQ>>>(x, out);
}

// round 6
// speedup vs baseline: 1.4191x; 1.0064x over previous
#include <cuda_runtime.h>
#include <cstdint>

// ---------------------------------------------------------------------------
// y[bi,co,ti,p] = sum_{ds,dt,ci} W[co,ci,ds,dt]*x[bi',ci,t2,p] + x
// tf32 mma.sync m16n8k8 implicit GEMM (tcgen05 unreachable: harness targets
// sm_100 without 'a').
// R5 base (conflict-free 32-bit LDS @ PADW=36, NPAD=200 asymmetric tiles,
// cost-sorted blocks) + 3-stage cp.async pipeline with single __syncthreads
// per k-iter + merged prep kernel (2 launches per call -> ncu hits conv_mma).
// ---------------------------------------------------------------------------

#define CCH 1024
#define TT 4
#define HW 196
#define NPAD 200
#define SSEG 4
#define BM 128
#define BN 112
#define BKI 32
#define PADW 36
#define STAGES 3

#define ASZ (BM * PADW)
#define BSZ (BN * PADW)
#define STAGE_FLOATS (ASZ + BSZ)
#define SMEM_REQ (STAGES * STAGE_FLOATS * 4)   // 103680 B, 2 CTAs/SM = 202.5KB

__device__ float g_Wt[9u * CCH * CCH];      // [tap][co][ci], tf32-rounded
__device__ float g_Xt[32u * NPAD * CCH];    // [z][p][ci],    tf32-rounded

// work order: heavy (nv=9) z's first, then nv=6, then nv=4
__constant__ int c_zorder[32] = {
    5, 6, 9, 10, 21, 22, 25, 26,          // nv=9
    4, 7, 8, 11, 20, 23, 24, 27,          // nv=6 (s in {1,2})
    1, 2, 13, 14, 17, 18, 29, 30,         // nv=6 (t in {1,2})
    0, 3, 12, 15, 16, 19, 28, 31          // nv=4
};

// ---------------------------- helpers --------------------------------------
__device__ __forceinline__ uint32_t f2tf32(float a) {
    uint32_t r; asm("cvt.rna.tf32.f32 %0, %1;" : "=r"(r) : "f"(a)); return r;
}
__device__ __forceinline__ void cp16(uint32_t dst, const void* src) {
    asm volatile("cp.async.cg.shared.global [%0], [%1], 16;" :: "r"(dst), "l"(src));
}
#define CP_COMMIT() asm volatile("cp.async.commit_group;" ::: "memory")
#define CP_WAIT1()  asm volatile("cp.async.wait_group 1;" ::: "memory")

__device__ __forceinline__ void mma_tf32(float* c, const uint32_t* a, const uint32_t* b) {
    asm volatile(
        "mma.sync.aligned.m16n8k8.row.col.f32.tf32.tf32.f32 "
        "{%0,%1,%2,%3}, {%4,%5,%6,%7}, {%8,%9}, {%0,%1,%2,%3};"
        : "+f"(c[0]), "+f"(c[1]), "+f"(c[2]), "+f"(c[3])
        : "r"(a[0]), "r"(a[1]), "r"(a[2]), "r"(a[3]), "r"(b[0]), "r"(b[1]));
}

// ---------------------------- merged prep kernel ----------------------------
// blocks [0,1024): Wt transpose; blocks [1024,8192): Xt transpose.
__global__ __launch_bounds__(256) void prep_all(const float* __restrict__ W,
                                                const float* __restrict__ x) {
    int b = blockIdx.x;
    if (b < 1024) {
        __shared__ float s[9216];
        int co = b;
        const float4* row4 = (const float4*)(W + (size_t)co * 9216);
        float4* s4 = (float4*)s;
        for (int i = threadIdx.x; i < 2304; i += 256) s4[i] = row4[i];
        __syncthreads();
        uint32_t* dst = (uint32_t*)g_Wt;
        for (int tap = 0; tap < 9; tap++) {
            uint32_t* d = dst + ((size_t)tap * CCH + co) * CCH;
            for (int ci = threadIdx.x; ci < CCH; ci += 256)
                d[ci] = f2tf32(s[ci * 9 + tap]);
        }
    } else {
        __shared__ float tile[32][33];
        int bb = b - 1024;
        int pt = bb % 7;                   // p-tile
        int cit = (bb / 7) & 31;           // ci-tile
        int z = bb / (7 * 32);             // bi*4 + t
        int p0 = pt * 32;
        int ci0 = cit * 32;
        int tx = threadIdx.x & 31, ty = threadIdx.x >> 5;   // 32 x 8
        #pragma unroll
        for (int j = 0; j < 4; j++) {
            int ci = ci0 + ty + j * 8;
            int p = p0 + tx;
            float v = 0.f;
            if (p < HW) v = x[(((size_t)((z >> 2) * CCH + ci)) * TT + (z & 3)) * HW + p];
            tile[ty + j * 8][tx] = v;
        }
        __syncthreads();
        uint32_t* dst = (uint32_t*)g_Xt;
        #pragma unroll
        for (int j = 0; j < 4; j++) {
            int p = p0 + ty + j * 8;
            int ci = ci0 + tx;
            if (p < NPAD)
                dst[((size_t)z * NPAD + p) * CCH + ci] = f2tf32(tile[tx][ty + j * 8]);
        }
    }
}

// ---------------------------- main kernel -----------------------------------
__global__ __launch_bounds__(256, 2) void conv_mma(
    const float* __restrict__ x, float* __restrict__ out)
{
    extern __shared__ float smem[];
    const int tid = threadIdx.x;
    const int wid = tid >> 5, lid = tid & 31;
    const int gid = lid >> 2, tig = lid & 3;
    const int warp_m = wid & 3;           // 4 warps in M: 32 rows each
    const int warp_n = wid >> 2;          // 2 warps in N

    const int bidl = blockIdx.x;          // 0..511, cost-sorted
    const int z    = c_zorder[bidl >> 4];
    const int tile = bidl & 15;
    const int ct   = tile >> 1;           // co-tile 0..7
    const int py   = tile & 1;            // p-tile 0..1
    const int bi = z >> 2, ti = z & 3;
    const int s_seg = bi & 3, bp = bi >> 2;
    const int co0 = ct * BM;
    const int p0  = py * BN;

    // nt trip count per warp: py=0 -> 7/7 (112 wide); py=1 -> 7/4 (88 wide)
    const int ntc = (py && warp_n) ? 4 : 7;
    const int bnr8 = (py ? 88 : 112) * 8;     // B 16B-chunks per stage

    // valid taps
    int taps[9], zsrc[9], nv = 0;
    #pragma unroll
    for (int ds = 0; ds < 3; ds++) {
        int s2 = s_seg + ds - 1;
        if (s2 < 0 || s2 >= SSEG) continue;
        #pragma unroll
        for (int dt = 0; dt < 3; dt++) {
            int t2 = ti + dt - 1;
            if (t2 < 0 || t2 >= TT) continue;
            taps[nv] = ds * 3 + dt;
            zsrc[nv] = (bp * SSEG + s2) * TT + t2;
            nv++;
        }
    }
    const int total = nv * (CCH / BKI);

    uint32_t smem_u = (uint32_t)__cvta_generic_to_shared(smem);

    float acc[2][7][4];
    #pragma unroll
    for (int mt = 0; mt < 2; mt++)
        #pragma unroll
        for (int nt = 0; nt < 7; nt++)
            #pragma unroll
            for (int r = 0; r < 4; r++) acc[mt][nt][r] = 0.f;

    auto load_stage = [&](int it, int st) {
        int idx = it >> 5, k0 = (it & 31) * BKI;
        const float* Wt = g_Wt + (size_t)taps[idx] * CCH * CCH + (size_t)co0 * CCH + k0;
        const float* Xz = g_Xt + (size_t)zsrc[idx] * NPAD * CCH + (size_t)p0 * CCH + k0;
        uint32_t aB = smem_u + st * (STAGE_FLOATS * 4);
        uint32_t bB = aB + ASZ * 4;
        #pragma unroll
        for (int i = 0; i < 4; i++) {
            int c = tid + i * 256;
            int row = c >> 3, cc = c & 7;
            cp16(aB + row * (PADW * 4) + cc * 16, Wt + (size_t)row * CCH + cc * 4);
        }
        #pragma unroll
        for (int i = 0; i < 4; i++) {
            int c = tid + i * 256;
            if (c < bnr8) {
                int row = c >> 3, cc = c & 7;
                cp16(bB + row * (PADW * 4) + cc * 16, Xz + (size_t)row * CCH + cc * 4);
            }
        }
    };

    load_stage(0, 0); CP_COMMIT();
    load_stage(1, 1); CP_COMMIT();

    int st = 0;
    for (int it = 0; it < total; it++) {
        CP_WAIT1();            // stage st resident
        __syncthreads();       // all warps past consume(it-1) -> stage (st+2)%3 free

        int nxst = st + 2; if (nxst >= STAGES) nxst -= STAGES;
        if (it + 2 < total) load_stage(it + 2, nxst);
        CP_COMMIT();           // commit always: keeps wait_group count exact

        const float* As = smem + st * STAGE_FLOATS;
        const float* Bs = As + ASZ;
        #pragma unroll
        for (int ks = 0; ks < 4; ks++) {
            int k = ks * 8 + tig;
            uint32_t a[2][4], b[7][2];
            #pragma unroll
            for (int mt = 0; mt < 2; mt++) {
                const uint32_t* ap = (const uint32_t*)(As + (warp_m * 32 + mt * 16 + gid) * PADW + k);
                a[mt][0] = ap[0];
                a[mt][1] = ap[8 * PADW];
                a[mt][2] = ap[4];
                a[mt][3] = ap[8 * PADW + 4];
            }
            #pragma unroll
            for (int nt = 0; nt < 7; nt++) {
                if (nt < ntc) {
                    const uint32_t* bp2 = (const uint32_t*)(Bs + (warp_n * 56 + nt * 8 + gid) * PADW + k);
                    b[nt][0] = bp2[0];
                    b[nt][1] = bp2[4];
                }
            }
            #pragma unroll
            for (int mt = 0; mt < 2; mt++)
                #pragma unroll
                for (int nt = 0; nt < 7; nt++)
                    if (nt < ntc) mma_tf32(acc[mt][nt], a[mt], b[nt]);
        }
        st = st + 1; if (st >= STAGES) st = 0;
    }

    // epilogue: residual add + store
    #pragma unroll
    for (int mt = 0; mt < 2; mt++) {
        #pragma unroll
        for (int nt = 0; nt < 7; nt++) {
            if (nt >= ntc) continue;
            int co = co0 + warp_m * 32 + mt * 16 + gid;
            int p  = p0 + warp_n * 56 + nt * 8 + tig * 2;
            if (p < HW) {
                size_t i0 = ((size_t)(bi * CCH + co) * TT + ti) * HW + p;
                float2 r0 = *(const float2*)&x[i0];
                float2 o0 = { acc[mt][nt][0] + r0.x, acc[mt][nt][1] + r0.y };
                *(float2*)&out[i0] = o0;
                size_t i1 = ((size_t)(bi * CCH + co + 8) * TT + ti) * HW + p;
                float2 r1 = *(const float2*)&x[i1];
                float2 o1 = { acc[mt][nt][2] + r1.x, acc[mt][nt][3] + r1.y };
                *(float2*)&out[i1] = o1;
            }
        }
    }
}

// ---------------------------- host launch -----------------------------------
extern "C" void kernel_launch(void* const* d_in, const int* in_sizes, int n_in,
                              void* d_out, int out_size) {
    const float* x = (const float*)d_in[0];   // (8,1024,4,14,14)
    const float* W = (const float*)d_in[1];   // (1024,1024,3,3)
    float* out = (float*)d_out;

    prep_all<<<1024 + 7 * 32 * 32, 256>>>(W, x);

    cudaFuncSetAttribute(conv_mma, cudaFuncAttributeMaxDynamicSharedMemorySize, SMEM_REQ);
    conv_mma<<<512, 256, SMEM_REQ>>>(x, out);
}

// round 8
// speedup vs baseline: 2.5484x; 1.7958x over previous
#include <cuda_runtime.h>
#include <cuda_fp16.h>
#include <cstdint>

// ---------------------------------------------------------------------------
// y[bi,co,ti,p] = sum_{ds,dt,ci} W[co,ci,ds,dt]*x[bi',ci,t2,p] + x
// fp16 mma.sync m16n8k16 (fp32 accum) implicit GEMM. fp16 mantissa == tf32
// mantissa (10 bits), inputs O(1) -> precision matches measured tf32 rel_err
// (~2.5e-4) at 2x MACs/instruction and half the smem traffic.
// Within-16 K-permutation (applied in prep) makes each MMA fragment a single
// LDS.64; row stride PADH=48 halves (24 words) gives a perfect 32-bank cover
// per half-warp phase (24*g mod 32 = {0,24,16,8}).
// Skeleton: 3-stage cp.async, 1 syncthreads/iter, NPAD=200 asymmetric tiles,
// cost-sorted block order.
// ---------------------------------------------------------------------------

#define CCH 1024
#define TT 4
#define HW 196
#define NPAD 200
#define SSEG 4
#define BM 128
#define BN 112
#define BKI 32
#define PADH 48                      // halves per smem row = 24 words
#define STAGES 3

#define ASZH (BM * PADH)             // 6144 halves
#define BSZH (BN * PADH)             // 5376 halves
#define STAGE_BYTES ((ASZH + BSZH) * 2)   // 23040 B
#define SMEM_REQ (STAGES * STAGE_BYTES)   // 69120 B

__device__ __half g_Wt[9u * CCH * CCH];      // [tap][co][perm16(ci)]
__device__ __half g_Xt[32u * NPAD * CCH];    // [z][p][perm16(ci)]

// heavy blocks first: nv=9, then nv=6, then nv=4
__constant__ int c_zorder[32] = {
    5, 6, 9, 10, 21, 22, 25, 26,
    4, 7, 8, 11, 20, 23, 24, 27,
    1, 2, 13, 14, 17, 18, 29, 30,
    0, 3, 12, 15, 16, 19, 28, 31
};

// logical k within 16 -> phys so {2t,2t+1,2t+8,2t+9} land at {4t..4t+3}
__device__ __forceinline__ int perm16(int ci) {
    int j = ci & 15;
    return (ci & ~15) | ((((j & 7) >> 1) << 2) + (j & 1) + ((j >> 3) << 1));
}

// ---------------------------- helpers --------------------------------------
__device__ __forceinline__ void cp16(uint32_t dst, const void* src) {
    asm volatile("cp.async.cg.shared.global [%0], [%1], 16;" :: "r"(dst), "l"(src));
}
#define CP_COMMIT() asm volatile("cp.async.commit_group;" ::: "memory")
#define CP_WAIT1()  asm volatile("cp.async.wait_group 1;" ::: "memory")

__device__ __forceinline__ void mma_f16(float* c, const uint32_t* a, const uint32_t* b) {
    asm volatile(
        "mma.sync.aligned.m16n8k16.row.col.f32.f16.f16.f32 "
        "{%0,%1,%2,%3}, {%4,%5,%6,%7}, {%8,%9}, {%0,%1,%2,%3};"
        : "+f"(c[0]), "+f"(c[1]), "+f"(c[2]), "+f"(c[3])
        : "r"(a[0]), "r"(a[1]), "r"(a[2]), "r"(a[3]), "r"(b[0]), "r"(b[1]));
}

// ---------------------------- merged prep kernel ----------------------------
__global__ __launch_bounds__(256) void prep_all(const float* __restrict__ W,
                                                const float* __restrict__ x) {
    int b = blockIdx.x;
    if (b < 1024) {
        __shared__ float s[9216];
        int co = b;
        const float4* row4 = (const float4*)(W + (size_t)co * 9216);
        float4* s4 = (float4*)s;
        for (int i = threadIdx.x; i < 2304; i += 256) s4[i] = row4[i];
        __syncthreads();
        for (int tap = 0; tap < 9; tap++) {
            __half* d = g_Wt + ((size_t)tap * CCH + co) * CCH;
            for (int ci = threadIdx.x; ci < CCH; ci += 256)
                d[perm16(ci)] = __float2half(s[ci * 9 + tap]);
        }
    } else {
        __shared__ float tile[32][33];
        int bb = b - 1024;
        int pt = bb % 7;
        int cit = (bb / 7) & 31;
        int z = bb / (7 * 32);
        int p0 = pt * 32;
        int ci0 = cit * 32;
        int tx = threadIdx.x & 31, ty = threadIdx.x >> 5;   // 32 x 8
        #pragma unroll
        for (int j = 0; j < 4; j++) {
            int ci = ci0 + ty + j * 8;
            int p = p0 + tx;
            float v = 0.f;
            if (p < HW) v = x[(((size_t)((z >> 2) * CCH + ci)) * TT + (z & 3)) * HW + p];
            tile[ty + j * 8][tx] = v;
        }
        __syncthreads();
        #pragma unroll
        for (int j = 0; j < 4; j++) {
            int p = p0 + ty + j * 8;
            int ci = ci0 + tx;
            if (p < NPAD)
                g_Xt[((size_t)z * NPAD + p) * CCH + perm16(ci)] =
                    __float2half(tile[tx][ty + j * 8]);
        }
    }
}

// ---------------------------- main kernel -----------------------------------
__global__ __launch_bounds__(256, 2) void conv_mma(
    const float* __restrict__ x, float* __restrict__ out)
{
    extern __shared__ __half smem[];
    const int tid = threadIdx.x;
    const int wid = tid >> 5, lid = tid & 31;
    const int gid = lid >> 2, tig = lid & 3;
    const int warp_m = wid & 3;           // 4 warps in M: 32 rows each
    const int warp_n = wid >> 2;          // 2 warps in N

    const int bidl = blockIdx.x;
    const int z    = c_zorder[bidl >> 4];
    const int tile = bidl & 15;
    const int ct   = tile >> 1;           // co-tile 0..7
    const int py   = tile & 1;            // p-tile 0..1
    const int bi = z >> 2, ti = z & 3;
    const int s_seg = bi & 3, bp = bi >> 2;
    const int co0 = ct * BM;
    const int p0  = py * BN;

    const int ntc  = (py && warp_n) ? 4 : 7;   // 112-wide vs 88-wide tile
    const int bnr4 = (py ? 88 : 112) * 4;      // B 16B-chunks per stage

    int taps[9], zsrc[9], nv = 0;
    #pragma unroll
    for (int ds = 0; ds < 3; ds++) {
        int s2 = s_seg + ds - 1;
        if (s2 < 0 || s2 >= SSEG) continue;
        #pragma unroll
        for (int dt = 0; dt < 3; dt++) {
            int t2 = ti + dt - 1;
            if (t2 < 0 || t2 >= TT) continue;
            taps[nv] = ds * 3 + dt;
            zsrc[nv] = (bp * SSEG + s2) * TT + t2;
            nv++;
        }
    }
    const int total = nv * (CCH / BKI);

    uint32_t smem_u = (uint32_t)__cvta_generic_to_shared(smem);

    float acc[2][7][4];
    #pragma unroll
    for (int mt = 0; mt < 2; mt++)
        #pragma unroll
        for (int nt = 0; nt < 7; nt++)
            #pragma unroll
            for (int r = 0; r < 4; r++) acc[mt][nt][r] = 0.f;

    auto load_stage = [&](int it, int st) {
        int idx = it >> 5, k0 = (it & 31) * BKI;
        const __half* Wt = g_Wt + (size_t)taps[idx] * CCH * CCH + (size_t)co0 * CCH + k0;
        const __half* Xz = g_Xt + (size_t)zsrc[idx] * NPAD * CCH + (size_t)p0 * CCH + k0;
        uint32_t aB = smem_u + st * STAGE_BYTES;
        uint32_t bB = aB + ASZH * 2;
        #pragma unroll
        for (int i = 0; i < 2; i++) {
            int c = tid + i * 256;               // 512 A chunks (128 rows x 4)
            int row = c >> 2, cc = c & 3;
            cp16(aB + row * (PADH * 2) + cc * 16, Wt + (size_t)row * CCH + cc * 8);
        }
        #pragma unroll
        for (int i = 0; i < 2; i++) {
            int c = tid + i * 256;
            if (c < bnr4) {
                int row = c >> 2, cc = c & 3;
                cp16(bB + row * (PADH * 2) + cc * 16, Xz + (size_t)row * CCH + cc * 8);
            }
        }
    };

    load_stage(0, 0); CP_COMMIT();
    load_stage(1, 1); CP_COMMIT();

    int st = 0;
    for (int it = 0; it < total; it++) {
        CP_WAIT1();
        __syncthreads();           // stage (st+2)%3 now free for refill

        int nxst = st + 2; if (nxst >= STAGES) nxst -= STAGES;
        if (it + 2 < total) load_stage(it + 2, nxst);
        CP_COMMIT();

        const __half* As = smem + (size_t)st * (ASZH + BSZH);
        const __half* Bs = As + ASZH;
        #pragma unroll
        for (int ks = 0; ks < 2; ks++) {          // two k16 steps per BK=32
            const int ko = ks * 16 + tig * 4;     // phys half offset of fragment
            uint32_t a[2][4], b[7][2];
            #pragma unroll
            for (int mt = 0; mt < 2; mt++) {
                int r0 = warp_m * 32 + mt * 16 + gid;
                uint2 v0 = *(const uint2*)(As + r0 * PADH + ko);        // a0,a2
                uint2 v1 = *(const uint2*)(As + (r0 + 8) * PADH + ko);  // a1,a3
                a[mt][0] = v0.x; a[mt][1] = v1.x; a[mt][2] = v0.y; a[mt][3] = v1.y;
            }
            #pragma unroll
            for (int nt = 0; nt < 7; nt++) {
                if (nt < ntc) {
                    uint2 v = *(const uint2*)(Bs + (warp_n * 56 + nt * 8 + gid) * PADH + ko);
                    b[nt][0] = v.x; b[nt][1] = v.y;
                }
            }
            #pragma unroll
            for (int mt = 0; mt < 2; mt++)
                #pragma unroll
                for (int nt = 0; nt < 7; nt++)
                    if (nt < ntc) mma_f16(acc[mt][nt], a[mt], b[nt]);
        }
        st = st + 1; if (st >= STAGES) st = 0;
    }

    // epilogue: residual add + store (same output fragment layout as m16n8k8)
    #pragma unroll
    for (int mt = 0; mt < 2; mt++) {
        #pragma unroll
        for (int nt = 0; nt < 7; nt++) {
            if (nt >= ntc) continue;
            int co = co0 + warp_m * 32 + mt * 16 + gid;
            int p  = p0 + warp_n * 56 + nt * 8 + tig * 2;
            if (p < HW) {
                size_t i0 = ((size_t)(bi * CCH + co) * TT + ti) * HW + p;
                float2 r0 = *(const float2*)&x[i0];
                float2 o0 = { acc[mt][nt][0] + r0.x, acc[mt][nt][1] + r0.y };
                *(float2*)&out[i0] = o0;
                size_t i1 = ((size_t)(bi * CCH + co + 8) * TT + ti) * HW + p;
                float2 r1 = *(const float2*)&x[i1];
                float2 o1 = { acc[mt][nt][2] + r1.x, acc[mt][nt][3] + r1.y };
                *(float2*)&out[i1] = o1;
            }
        }
    }
}

// ---------------------------- host launch -----------------------------------
extern "C" void kernel_launch(void* const* d_in, const int* in_sizes, int n_in,
                              void* d_out, int out_size) {
    const float* x = (const float*)d_in[0];   // (8,1024,4,14,14)
    const float* W = (const float*)d_in[1];   // (1024,1024,3,3)
    float* out = (float*)d_out;

    prep_all<<<1024 + 7 * 32 * 32, 256>>>(W, x);

    cudaFuncSetAttribute(conv_mma, cudaFuncAttributeMaxDynamicSharedMemorySize, SMEM_REQ);
    conv_mma<<<512, 256, SMEM_REQ>>>(x, out);
}